// round 2
// baseline (speedup 1.0000x reference)
#include <cuda_runtime.h>
#include <cuda_bf16.h>
#include <math.h>

// Problem constants
#define BATCH 2
#define SEQ   2048
#define DMODEL 1024
#define NHEADS 16
#define DK    64
#define MROWS (BATCH * SEQ)     // 4096
#define ATT_SCALE 0.125f        // 1/sqrt(64)

// ---------------- scratch (device globals; no cudaMalloc allowed) ----------
__device__ float g_Q[MROWS * DMODEL];
__device__ float g_K[MROWS * DMODEL];
__device__ float g_V[MROWS * DMODEL];
__device__ float g_O[MROWS * DMODEL];

// ---------------- GEMM: C[M,N] = A[M,K] * B[N,K]^T (both row-major) --------
#define TBM 64
#define TBN 64
#define TBK 16

__global__ __launch_bounds__(256) void gemm_nt(const float* __restrict__ A,
                                               const float* __restrict__ Bm,
                                               float* __restrict__ C,
                                               int M, int N, int K) {
    __shared__ float As[TBK][TBM + 4];
    __shared__ float Bs[TBK][TBN + 4];

    const int tid = threadIdx.x;
    const int tx = tid & 15;
    const int ty = tid >> 4;
    const int rowBase = blockIdx.y * TBM;
    const int colBase = blockIdx.x * TBN;

    float acc[4][4] = {};

    const int lr = tid >> 2;        // 0..63 row within tile
    const int lc = (tid & 3) * 4;   // 0,4,8,12 k-offset

    for (int k0 = 0; k0 < K; k0 += TBK) {
        float4 va = *reinterpret_cast<const float4*>(&A[(size_t)(rowBase + lr) * K + k0 + lc]);
        As[lc + 0][lr] = va.x; As[lc + 1][lr] = va.y;
        As[lc + 2][lr] = va.z; As[lc + 3][lr] = va.w;
        float4 vb = *reinterpret_cast<const float4*>(&Bm[(size_t)(colBase + lr) * K + k0 + lc]);
        Bs[lc + 0][lr] = vb.x; Bs[lc + 1][lr] = vb.y;
        Bs[lc + 2][lr] = vb.z; Bs[lc + 3][lr] = vb.w;
        __syncthreads();

#pragma unroll
        for (int kk = 0; kk < TBK; kk++) {
            float a[4], b[4];
#pragma unroll
            for (int i = 0; i < 4; i++) a[i] = As[kk][ty * 4 + i];
#pragma unroll
            for (int j = 0; j < 4; j++) b[j] = Bs[kk][tx * 4 + j];
#pragma unroll
            for (int i = 0; i < 4; i++)
#pragma unroll
                for (int j = 0; j < 4; j++)
                    acc[i][j] += a[i] * b[j];
        }
        __syncthreads();
    }

#pragma unroll
    for (int i = 0; i < 4; i++) {
        float4 o = make_float4(acc[i][0], acc[i][1], acc[i][2], acc[i][3]);
        *reinterpret_cast<float4*>(&C[(size_t)(rowBase + ty * 4 + i) * N + colBase + tx * 4]) = o;
    }
}

// ---------------- Flash attention kernel -----------------------------------
// grid: (SEQ/64, BATCH*NHEADS), block: 256 threads
// smem: Qs[d][q] (64x72), KP (Ks[d][k] 64x72 then reused as Ps[q][k] 64x72),
//       Vs[k][d] (64x72)
#define SSTR 72
#define FLASH_SMEM (3 * 64 * SSTR * 4)

__global__ __launch_bounds__(256) void flash_attn(const float* __restrict__ Q,
                                                  const float* __restrict__ K,
                                                  const float* __restrict__ V,
                                                  float* __restrict__ O) {
    extern __shared__ float sm[];
    float* Qs = sm;                   // Qs[d*SSTR + q]
    float* KP = sm + 64 * SSTR;       // Ks[d*SSTR + k] / Ps[q*SSTR + k]
    float* Vs = sm + 2 * 64 * SSTR;   // Vs[k*SSTR + d]

    const int tid = threadIdx.x;
    const int tx = tid & 15;
    const int ty = tid >> 4;

    const int bh = blockIdx.y;
    const int b  = bh / NHEADS;
    const int h  = bh % NHEADS;
    const int qBase = blockIdx.x * 64;

    const int lr = tid >> 2;          // 0..63 (row within tile)
    const int ld = (tid & 3) * 16;    // 0,16,32,48 (d offset; 4 float4 each)

    // Load Q tile transposed: Qs[d][q]
    {
        const float* qp = Q + (size_t)(b * SEQ + qBase + lr) * DMODEL + h * DK + ld;
#pragma unroll
        for (int u = 0; u < 4; u++) {
            float4 v = *reinterpret_cast<const float4*>(qp + u * 4);
            int d = ld + u * 4;
            Qs[(d + 0) * SSTR + lr] = v.x;
            Qs[(d + 1) * SSTR + lr] = v.y;
            Qs[(d + 2) * SSTR + lr] = v.z;
            Qs[(d + 3) * SSTR + lr] = v.w;
        }
    }

    float m[4], l[4], o[4][4];
#pragma unroll
    for (int i = 0; i < 4; i++) {
        m[i] = -INFINITY; l[i] = 0.f;
#pragma unroll
        for (int j = 0; j < 4; j++) o[i][j] = 0.f;
    }

    const int nTiles = SEQ / 64;
    for (int kt = 0; kt < nTiles; kt++) {
        __syncthreads();  // previous iter's KP/Vs fully consumed
        // Load K tile transposed Ks[d][k]; V tile natural Vs[k][d]
        {
            const float* kp = K + (size_t)(b * SEQ + kt * 64 + lr) * DMODEL + h * DK + ld;
            const float* vp = V + (size_t)(b * SEQ + kt * 64 + lr) * DMODEL + h * DK + ld;
#pragma unroll
            for (int u = 0; u < 4; u++) {
                float4 v = *reinterpret_cast<const float4*>(kp + u * 4);
                int d = ld + u * 4;
                KP[(d + 0) * SSTR + lr] = v.x;
                KP[(d + 1) * SSTR + lr] = v.y;
                KP[(d + 2) * SSTR + lr] = v.z;
                KP[(d + 3) * SSTR + lr] = v.w;
                float4 w = *reinterpret_cast<const float4*>(vp + u * 4);
                *reinterpret_cast<float4*>(&Vs[lr * SSTR + ld + u * 4]) = w;
            }
        }
        __syncthreads();

        // s = (Q K^T) * scale  -- thread owns queries ty*4+i, keys tx*4+j
        float s[4][4] = {};
#pragma unroll 8
        for (int d = 0; d < DK; d++) {
            float a[4], bk[4];
#pragma unroll
            for (int i = 0; i < 4; i++) a[i] = Qs[d * SSTR + ty * 4 + i];
#pragma unroll
            for (int j = 0; j < 4; j++) bk[j] = KP[d * SSTR + tx * 4 + j];
#pragma unroll
            for (int i = 0; i < 4; i++)
#pragma unroll
                for (int j = 0; j < 4; j++)
                    s[i][j] += a[i] * bk[j];
        }

        // Online softmax update (per query row; 16 tx lanes share a row)
        float alpha[4];
#pragma unroll
        for (int i = 0; i < 4; i++) {
            float rm = s[i][0];
#pragma unroll
            for (int j = 1; j < 4; j++) rm = fmaxf(rm, s[i][j]);
            rm *= ATT_SCALE;
#pragma unroll
            for (int off = 8; off > 0; off >>= 1)
                rm = fmaxf(rm, __shfl_xor_sync(0xffffffffu, rm, off));
            float mn = fmaxf(m[i], rm);
            alpha[i] = __expf(m[i] - mn);
            m[i] = mn;
            float rs = 0.f;
#pragma unroll
            for (int j = 0; j < 4; j++) {
                s[i][j] = __expf(s[i][j] * ATT_SCALE - mn);
                rs += s[i][j];
            }
#pragma unroll
            for (int off = 8; off > 0; off >>= 1)
                rs += __shfl_xor_sync(0xffffffffu, rs, off);
            l[i] = l[i] * alpha[i] + rs;
#pragma unroll
            for (int j = 0; j < 4; j++) o[i][j] *= alpha[i];
        }

        __syncthreads();  // done reading Ks; reuse KP as Ps[q][k]
#pragma unroll
        for (int i = 0; i < 4; i++) {
            float4 p4 = make_float4(s[i][0], s[i][1], s[i][2], s[i][3]);
            *reinterpret_cast<float4*>(&KP[(ty * 4 + i) * SSTR + tx * 4]) = p4;
        }
        __syncthreads();

        // o[q][d] += P[q][k] * V[k][d]  -- thread owns queries ty*4+i, d = tx*4+j
#pragma unroll 8
        for (int kk = 0; kk < 64; kk++) {
            float p[4], vv[4];
#pragma unroll
            for (int i = 0; i < 4; i++) p[i] = KP[(ty * 4 + i) * SSTR + kk];
#pragma unroll
            for (int j = 0; j < 4; j++) vv[j] = Vs[kk * SSTR + tx * 4 + j];
#pragma unroll
            for (int i = 0; i < 4; i++)
#pragma unroll
                for (int j = 0; j < 4; j++)
                    o[i][j] += p[i] * vv[j];
        }
    }

    // Epilogue: divide by l, write to O in [B,S,D] layout (undo head split)
#pragma unroll
    for (int i = 0; i < 4; i++) {
        float inv = 1.f / l[i];
        float4 ov = make_float4(o[i][0] * inv, o[i][1] * inv, o[i][2] * inv, o[i][3] * inv);
        *reinterpret_cast<float4*>(
            &O[(size_t)(b * SEQ + qBase + ty * 4 + i) * DMODEL + h * DK + tx * 4]) = ov;
    }
}

// ---------------- launch ---------------------------------------------------
extern "C" void kernel_launch(void* const* d_in, const int* in_sizes, int n_in,
                              void* d_out, int out_size) {
    const float* x  = (const float*)d_in[0];
    const float* Wq = (const float*)d_in[1];
    const float* Wk = (const float*)d_in[2];
    const float* Wv = (const float*)d_in[3];
    const float* Wo = (const float*)d_in[4];
    float* out = (float*)d_out;

    float *Qp, *Kp, *Vp, *Op;
    cudaGetSymbolAddress((void**)&Qp, g_Q);
    cudaGetSymbolAddress((void**)&Kp, g_K);
    cudaGetSymbolAddress((void**)&Vp, g_V);
    cudaGetSymbolAddress((void**)&Op, g_O);

    cudaFuncSetAttribute(flash_attn, cudaFuncAttributeMaxDynamicSharedMemorySize,
                         FLASH_SMEM);

    dim3 gGemm(DMODEL / TBN, MROWS / TBM);  // (16, 64)
    gemm_nt<<<gGemm, 256>>>(x, Wq, Qp, MROWS, DMODEL, DMODEL);
    gemm_nt<<<gGemm, 256>>>(x, Wk, Kp, MROWS, DMODEL, DMODEL);
    gemm_nt<<<gGemm, 256>>>(x, Wv, Vp, MROWS, DMODEL, DMODEL);

    dim3 gFlash(SEQ / 64, BATCH * NHEADS);  // (32, 32)
    flash_attn<<<gFlash, 256, FLASH_SMEM>>>(Qp, Kp, Vp, Op);

    gemm_nt<<<gGemm, 256>>>(Op, Wo, out, MROWS, DMODEL, DMODEL);
}

// round 3
// speedup vs baseline: 2.7156x; 2.7156x over previous
#include <cuda_runtime.h>
#include <cuda_bf16.h>
#include <cstdint>
#include <math.h>

// Problem constants
#define BATCH 2
#define SEQ   2048
#define DMODEL 1024
#define NHEADS 16
#define DK    64
#define MROWS (BATCH * SEQ)     // 4096
#define ATT_SCALE 0.125f        // 1/sqrt(64)

// ---------------- scratch (device globals; no cudaMalloc allowed) ----------
__device__ float g_Q[MROWS * DMODEL];
__device__ float g_K[MROWS * DMODEL];
__device__ float g_V[MROWS * DMODEL];
__device__ float g_O[MROWS * DMODEL];

// ---------------- helpers ---------------------------------------------------
__device__ __forceinline__ uint32_t f2tf(float f) {
    uint32_t u;
    asm("cvt.rna.tf32.f32 %0, %1;" : "=r"(u) : "f"(f));
    return u;
}

__device__ __forceinline__ void mma_tf32(float c[4],
                                         uint32_t a0, uint32_t a1, uint32_t a2, uint32_t a3,
                                         uint32_t b0, uint32_t b1) {
    asm volatile(
        "mma.sync.aligned.m16n8k8.row.col.f32.tf32.tf32.f32 "
        "{%0,%1,%2,%3}, {%4,%5,%6,%7}, {%8,%9}, {%0,%1,%2,%3};"
        : "+f"(c[0]), "+f"(c[1]), "+f"(c[2]), "+f"(c[3])
        : "r"(a0), "r"(a1), "r"(a2), "r"(a3), "r"(b0), "r"(b1));
}

// ---------------- GEMM: C[M,N] = A[M,K] * B[N,K]^T  (tf32 tensor core) -----
// Block 256 threads (8 warps, 2x4), tile 128x128, k-chunk 32.
#define GMT 128
#define GNT 128
#define GKT 32
#define GSTR 36

__global__ __launch_bounds__(256) void gemm_nt_tc(const float* __restrict__ A,
                                                  const float* __restrict__ Bm,
                                                  float* __restrict__ C,
                                                  int M, int N, int K) {
    __shared__ uint32_t As[GMT * GSTR];
    __shared__ uint32_t Bs[GNT * GSTR];

    const int tid  = threadIdx.x;
    const int lane = tid & 31;
    const int warp = tid >> 5;
    const int g  = lane >> 2;      // 0..7
    const int tq = lane & 3;       // 0..3
    const int wm = (warp & 1) * 64;
    const int wn = (warp >> 1) * 32;
    const int rowBase = blockIdx.y * GMT;
    const int colBase = blockIdx.x * GNT;

    float acc[4][4][4];
#pragma unroll
    for (int i = 0; i < 4; i++)
#pragma unroll
        for (int j = 0; j < 4; j++)
#pragma unroll
            for (int t = 0; t < 4; t++) acc[i][j][t] = 0.f;

    const int lr = tid >> 1;            // 0..127
    const int lc = (tid & 1) * 16;      // 0 or 16
    const float* Ap = A  + (size_t)(rowBase + lr) * K + lc;
    const float* Bp = Bm + (size_t)(colBase + lr) * K + lc;

    for (int k0 = 0; k0 < K; k0 += GKT) {
#pragma unroll
        for (int u = 0; u < 4; u++) {
            float4 va = *reinterpret_cast<const float4*>(Ap + k0 + u * 4);
            uint32_t* d = &As[lr * GSTR + lc + u * 4];
            d[0] = f2tf(va.x); d[1] = f2tf(va.y); d[2] = f2tf(va.z); d[3] = f2tf(va.w);
            float4 vb = *reinterpret_cast<const float4*>(Bp + k0 + u * 4);
            uint32_t* e = &Bs[lr * GSTR + lc + u * 4];
            e[0] = f2tf(vb.x); e[1] = f2tf(vb.y); e[2] = f2tf(vb.z); e[3] = f2tf(vb.w);
        }
        __syncthreads();

#pragma unroll
        for (int ks = 0; ks < 4; ks++) {
            const int kk = ks * 8;
            uint32_t a[4][4], b[4][2];
#pragma unroll
            for (int i = 0; i < 4; i++) {
                a[i][0] = As[(wm + 16 * i + g) * GSTR + kk + tq];
                a[i][1] = As[(wm + 16 * i + g + 8) * GSTR + kk + tq];
                a[i][2] = As[(wm + 16 * i + g) * GSTR + kk + tq + 4];
                a[i][3] = As[(wm + 16 * i + g + 8) * GSTR + kk + tq + 4];
            }
#pragma unroll
            for (int j = 0; j < 4; j++) {
                b[j][0] = Bs[(wn + 8 * j + g) * GSTR + kk + tq];
                b[j][1] = Bs[(wn + 8 * j + g) * GSTR + kk + tq + 4];
            }
#pragma unroll
            for (int i = 0; i < 4; i++)
#pragma unroll
                for (int j = 0; j < 4; j++)
                    mma_tf32(acc[i][j], a[i][0], a[i][1], a[i][2], a[i][3],
                             b[j][0], b[j][1]);
        }
        __syncthreads();
    }

#pragma unroll
    for (int i = 0; i < 4; i++) {
        const int r0 = rowBase + wm + 16 * i + g;
#pragma unroll
        for (int j = 0; j < 4; j++) {
            const int c0 = colBase + wn + 8 * j + 2 * tq;
            *reinterpret_cast<float2*>(&C[(size_t)r0 * N + c0]) =
                make_float2(acc[i][j][0], acc[i][j][1]);
            *reinterpret_cast<float2*>(&C[(size_t)(r0 + 8) * N + c0]) =
                make_float2(acc[i][j][2], acc[i][j][3]);
        }
    }
}

// ---------------- Flash attention (tf32 tensor core) ------------------------
// Block 256 threads (8 warps), 128-query tile, 64-key tiles.
// Warp w owns query rows 16w..16w+15 (one m16 fragment row).
#define QT 128
#define KT 64
#define QSTR 68
#define KSTR 68
#define VSTR 72
#define PSTR 68
#define OFF_Q 0
#define OFF_K (QT * QSTR)               // 8704
#define OFF_V (OFF_K + KT * KSTR)       // 13056
#define OFF_P (OFF_V + KT * VSTR)       // 17664
#define FLASH_WORDS (OFF_P + QT * PSTR) // 26368
#define FLASH_SMEM (FLASH_WORDS * 4)    // 105472 B

__global__ __launch_bounds__(256) void flash_tc(const float* __restrict__ Q,
                                                const float* __restrict__ K,
                                                const float* __restrict__ V,
                                                float* __restrict__ O) {
    extern __shared__ uint32_t sm[];
    uint32_t* Qs = sm + OFF_Q;
    uint32_t* Ks = sm + OFF_K;
    uint32_t* Vs = sm + OFF_V;
    uint32_t* Ps = sm + OFF_P;

    const int tid  = threadIdx.x;
    const int lane = tid & 31;
    const int warp = tid >> 5;
    const int g  = lane >> 2;
    const int tq = lane & 3;
    const int r0 = warp * 16;

    const int bh = blockIdx.y;
    const int b  = bh / NHEADS;
    const int h  = bh % NHEADS;
    const int qBase = blockIdx.x * QT;

    // Load Q tile (128 x 64), convert to tf32
    {
        const int lr = tid >> 1;
        const int lc = (tid & 1) * 32;
        const float* qp = Q + (size_t)(b * SEQ + qBase + lr) * DMODEL + h * DK + lc;
#pragma unroll
        for (int u = 0; u < 8; u++) {
            float4 v = *reinterpret_cast<const float4*>(qp + u * 4);
            uint32_t* d = &Qs[lr * QSTR + lc + u * 4];
            d[0] = f2tf(v.x); d[1] = f2tf(v.y); d[2] = f2tf(v.z); d[3] = f2tf(v.w);
        }
    }

    float m0 = -INFINITY, m1 = -INFINITY, l0 = 0.f, l1 = 0.f;
    float o[8][4];
#pragma unroll
    for (int j = 0; j < 8; j++)
#pragma unroll
        for (int t = 0; t < 4; t++) o[j][t] = 0.f;

    for (int kt = 0; kt < SEQ / KT; kt++) {
        __syncthreads();  // prev iter's Ks/Vs fully consumed
        {
            const int lr = tid >> 2;
            const int lc = (tid & 3) * 16;
            const float* kp = K + (size_t)(b * SEQ + kt * KT + lr) * DMODEL + h * DK + lc;
            const float* vp = V + (size_t)(b * SEQ + kt * KT + lr) * DMODEL + h * DK + lc;
#pragma unroll
            for (int u = 0; u < 4; u++) {
                float4 v = *reinterpret_cast<const float4*>(kp + u * 4);
                uint32_t* d = &Ks[lr * KSTR + lc + u * 4];
                d[0] = f2tf(v.x); d[1] = f2tf(v.y); d[2] = f2tf(v.z); d[3] = f2tf(v.w);
                float4 w = *reinterpret_cast<const float4*>(vp + u * 4);
                uint32_t* e = &Vs[lr * VSTR + lc + u * 4];
                e[0] = f2tf(w.x); e[1] = f2tf(w.y); e[2] = f2tf(w.z); e[3] = f2tf(w.w);
            }
        }
        __syncthreads();

        // S = Q Kt^T  (16 x 64 per warp)
        float s[8][4];
#pragma unroll
        for (int j = 0; j < 8; j++)
#pragma unroll
            for (int t = 0; t < 4; t++) s[j][t] = 0.f;

#pragma unroll
        for (int ks = 0; ks < 8; ks++) {
            const int kk = ks * 8;
            uint32_t a0 = Qs[(r0 + g) * QSTR + kk + tq];
            uint32_t a1 = Qs[(r0 + g + 8) * QSTR + kk + tq];
            uint32_t a2 = Qs[(r0 + g) * QSTR + kk + tq + 4];
            uint32_t a3 = Qs[(r0 + g + 8) * QSTR + kk + tq + 4];
#pragma unroll
            for (int j = 0; j < 8; j++) {
                uint32_t b0 = Ks[(8 * j + g) * KSTR + kk + tq];
                uint32_t b1 = Ks[(8 * j + g) * KSTR + kk + tq + 4];
                mma_tf32(s[j], a0, a1, a2, a3, b0, b1);
            }
        }

        // Online softmax. Thread owns rows (r0+g) and (r0+g+8).
        float rm0 = -INFINITY, rm1 = -INFINITY;
#pragma unroll
        for (int j = 0; j < 8; j++) {
            s[j][0] *= ATT_SCALE; s[j][1] *= ATT_SCALE;
            s[j][2] *= ATT_SCALE; s[j][3] *= ATT_SCALE;
            rm0 = fmaxf(rm0, fmaxf(s[j][0], s[j][1]));
            rm1 = fmaxf(rm1, fmaxf(s[j][2], s[j][3]));
        }
        rm0 = fmaxf(rm0, __shfl_xor_sync(0xffffffffu, rm0, 1));
        rm0 = fmaxf(rm0, __shfl_xor_sync(0xffffffffu, rm0, 2));
        rm1 = fmaxf(rm1, __shfl_xor_sync(0xffffffffu, rm1, 1));
        rm1 = fmaxf(rm1, __shfl_xor_sync(0xffffffffu, rm1, 2));

        const float mn0 = fmaxf(m0, rm0);
        const float mn1 = fmaxf(m1, rm1);
        const float al0 = __expf(m0 - mn0);
        const float al1 = __expf(m1 - mn1);
        m0 = mn0; m1 = mn1;

        float rs0 = 0.f, rs1 = 0.f;
        __syncwarp();  // all lanes done reading Ps from previous PV
#pragma unroll
        for (int j = 0; j < 8; j++) {
            float p0 = __expf(s[j][0] - mn0);
            float p1 = __expf(s[j][1] - mn0);
            float p2 = __expf(s[j][2] - mn1);
            float p3 = __expf(s[j][3] - mn1);
            rs0 += p0 + p1; rs1 += p2 + p3;
            Ps[(r0 + g) * PSTR + 8 * j + 2 * tq]         = f2tf(p0);
            Ps[(r0 + g) * PSTR + 8 * j + 2 * tq + 1]     = f2tf(p1);
            Ps[(r0 + g + 8) * PSTR + 8 * j + 2 * tq]     = f2tf(p2);
            Ps[(r0 + g + 8) * PSTR + 8 * j + 2 * tq + 1] = f2tf(p3);
        }
        rs0 += __shfl_xor_sync(0xffffffffu, rs0, 1);
        rs0 += __shfl_xor_sync(0xffffffffu, rs0, 2);
        rs1 += __shfl_xor_sync(0xffffffffu, rs1, 1);
        rs1 += __shfl_xor_sync(0xffffffffu, rs1, 2);
        l0 = l0 * al0 + rs0;
        l1 = l1 * al1 + rs1;

#pragma unroll
        for (int j = 0; j < 8; j++) {
            o[j][0] *= al0; o[j][1] *= al0;
            o[j][2] *= al1; o[j][3] *= al1;
        }
        __syncwarp();  // Ps writes visible to all lanes of this warp

        // O += P V  (16 x 64 per warp)
#pragma unroll
        for (int ks = 0; ks < 8; ks++) {
            const int kk = ks * 8;
            uint32_t a0 = Ps[(r0 + g) * PSTR + kk + tq];
            uint32_t a1 = Ps[(r0 + g + 8) * PSTR + kk + tq];
            uint32_t a2 = Ps[(r0 + g) * PSTR + kk + tq + 4];
            uint32_t a3 = Ps[(r0 + g + 8) * PSTR + kk + tq + 4];
#pragma unroll
            for (int j = 0; j < 8; j++) {
                uint32_t b0 = Vs[(kk + tq) * VSTR + 8 * j + g];
                uint32_t b1 = Vs[(kk + tq + 4) * VSTR + 8 * j + g];
                mma_tf32(o[j], a0, a1, a2, a3, b0, b1);
            }
        }
    }

    // Epilogue: normalize and store (undo head split)
    const float inv0 = 1.f / l0;
    const float inv1 = 1.f / l1;
    const size_t row0 = (size_t)(b * SEQ + qBase + r0 + g);
#pragma unroll
    for (int j = 0; j < 8; j++) {
        const int c = h * DK + 8 * j + 2 * tq;
        *reinterpret_cast<float2*>(&O[row0 * DMODEL + c]) =
            make_float2(o[j][0] * inv0, o[j][1] * inv0);
        *reinterpret_cast<float2*>(&O[(row0 + 8) * DMODEL + c]) =
            make_float2(o[j][2] * inv1, o[j][3] * inv1);
    }
}

// ---------------- launch ---------------------------------------------------
extern "C" void kernel_launch(void* const* d_in, const int* in_sizes, int n_in,
                              void* d_out, int out_size) {
    const float* x  = (const float*)d_in[0];
    const float* Wq = (const float*)d_in[1];
    const float* Wk = (const float*)d_in[2];
    const float* Wv = (const float*)d_in[3];
    const float* Wo = (const float*)d_in[4];
    float* out = (float*)d_out;

    float *Qp, *Kp, *Vp, *Op;
    cudaGetSymbolAddress((void**)&Qp, g_Q);
    cudaGetSymbolAddress((void**)&Kp, g_K);
    cudaGetSymbolAddress((void**)&Vp, g_V);
    cudaGetSymbolAddress((void**)&Op, g_O);

    cudaFuncSetAttribute(flash_tc, cudaFuncAttributeMaxDynamicSharedMemorySize,
                         FLASH_SMEM);

    dim3 gGemm(DMODEL / GNT, MROWS / GMT);  // (8, 32)
    gemm_nt_tc<<<gGemm, 256>>>(x, Wq, Qp, MROWS, DMODEL, DMODEL);
    gemm_nt_tc<<<gGemm, 256>>>(x, Wk, Kp, MROWS, DMODEL, DMODEL);
    gemm_nt_tc<<<gGemm, 256>>>(x, Wv, Vp, MROWS, DMODEL, DMODEL);

    dim3 gFlash(SEQ / QT, BATCH * NHEADS);  // (16, 32)
    flash_tc<<<gFlash, 256, FLASH_SMEM>>>(Qp, Kp, Vp, Op);

    gemm_nt_tc<<<gGemm, 256>>>(Op, Wo, out, MROWS, DMODEL, DMODEL);
}